// round 14
// baseline (speedup 1.0000x reference)
#include <cuda_runtime.h>
#include <cuda_fp16.h>
#include <cstddef>

#define NC 100000
#define NE 200000
#define NV 150000
#define NTOT (2*NC + NE + NV)            // 550000 counters (type-concatenated)
#define SCAN_BLK 256
#define SCAN_ITEMS 16
#define SCAN_TILE (SCAN_BLK*SCAN_ITEMS)  // 4096
#define NSCAN ((NTOT + SCAN_TILE - 1)/SCAN_TILE)

// ---------------- scratch (static device globals) ----------------
__device__ int    g_cnt[NTOT];      // zeroed per run
__device__ float  g_aggP[NC * 4];   // zeroed per run: aggP0 | aggP1 (2 floats each)
__device__ int    g_rowstart[NTOT];
__device__ int    g_cursor[NTOT];
__device__ int    g_bsum[NSCAN];
__device__ int    g_csr[4 * 2000000];
__device__ __half g_xh[(NC + NE + NV) * 64];   // fp16 copies: claim | entity | evid
__device__ float  g_pc[NC * 2];     // relu(h1_claim) @ ur
__device__ float  g_pe[NE * 2];     // relu(h1_entity) @ u0
__device__ float  g_pv[NV * 2];     // relu(h1_evid) @ u1
__device__ float  g_Wr1c[64 * 64];  // Wr1[0] + Wr1[1]
__device__ float  g_b1c[64];        // bl1[0] + bl1[1]
__device__ float  g_u0[128];        // Wl2[0] @ Wc
__device__ float  g_u1[128];        // Wl2[1] @ Wc
__device__ float  g_ur[128];        // (Wr2[0]+Wr2[1]) @ Wc
__device__ float  g_b2[2];          // (bl2[0]+bl2[1]) @ Wc + bc

__device__ __forceinline__ int type_off(int t) {
    return (t == 0) ? 0 : (t == 1) ? NC : (t == 2) ? 2 * NC : 2 * NC + NE;
}

// ---------------- tiny weight prep ----------------
__global__ void prep_kernel(const float* __restrict__ Wr1, const float* __restrict__ bl1,
                            const float* __restrict__ Wl2, const float* __restrict__ bl2,
                            const float* __restrict__ Wr2, const float* __restrict__ Wc,
                            const float* __restrict__ bc)
{
    int tid = threadIdx.x;
    for (int idx = tid; idx < 4096; idx += 256)
        g_Wr1c[idx] = Wr1[idx] + Wr1[4096 + idx];
    if (tid < 64) g_b1c[tid] = bl1[tid] + bl1[64 + tid];
    if (tid < 128) {
        int i = tid >> 1, c = tid & 1;
        float s0 = 0.f, s1 = 0.f, sr = 0.f;
        for (int j = 0; j < 64; j++) {
            float wc = Wc[j * 2 + c];
            s0 += Wl2[i * 64 + j] * wc;
            s1 += Wl2[4096 + i * 64 + j] * wc;
            sr += (Wr2[i * 64 + j] + Wr2[4096 + i * 64 + j]) * wc;
        }
        g_u0[tid] = s0; g_u1[tid] = s1; g_ur[tid] = sr;
    }
    if (tid < 2) {
        float s = bc[tid];
        for (int j = 0; j < 64; j++) s += (bl2[j] + bl2[64 + j]) * Wc[j * 2 + tid];
        g_b2[tid] = s;
    }
}

// ---------------- fp32 -> fp16 feature conversion (all three tensors, one launch) ----------------
struct THArgs { const float4* src[3]; __half2* dst[3]; int n4[3]; };

__global__ void tohalf_kernel(THArgs a)
{
    int t = blockIdx.y;
    int i = blockIdx.x * blockDim.x + threadIdx.x;
    if (i >= a.n4[t]) return;
    float4 v = __ldg(a.src[t] + i);
    a.dst[t][2 * i]     = __floats2half2_rn(v.x, v.y);
    a.dst[t][2 * i + 1] = __floats2half2_rn(v.z, v.w);
}

// ---------------- CSR build: histogram / scan / permute ----------------
__global__ void hist_kernel(const int* __restrict__ ei, int E)
{
    int t = blockIdx.y;
    int e = blockIdx.x * blockDim.x + threadIdx.x;
    if (e >= E) return;
    const int* dst = ei + (size_t)(2 * t + 1) * E;
    atomicAdd(&g_cnt[type_off(t) + __ldg(dst + e)], 1);
}

__global__ void scan1_kernel()
{
    __shared__ int s[SCAN_BLK];
    int base = blockIdx.x * SCAN_TILE + threadIdx.x * SCAN_ITEMS;
    int sum = 0;
#pragma unroll
    for (int i = 0; i < SCAN_ITEMS; i++) {
        int idx = base + i;
        if (idx < NTOT) sum += g_cnt[idx];
    }
    s[threadIdx.x] = sum;
    __syncthreads();
    for (int o = SCAN_BLK / 2; o > 0; o >>= 1) {
        if (threadIdx.x < o) s[threadIdx.x] += s[threadIdx.x + o];
        __syncthreads();
    }
    if (threadIdx.x == 0) g_bsum[blockIdx.x] = s[0];
}

__global__ void scan3_kernel()
{
    __shared__ int s[SCAN_BLK];
    __shared__ int boffs;
    int tid = threadIdx.x;

    if (tid < 32) {
        int sum = 0;
        for (int i = tid; i < blockIdx.x; i += 32) sum += g_bsum[i];
#pragma unroll
        for (int o = 16; o > 0; o >>= 1)
            sum += __shfl_down_sync(0xffffffffu, sum, o);
        if (tid == 0) boffs = sum;
    }

    int base = blockIdx.x * SCAN_TILE + tid * SCAN_ITEMS;
    int local[SCAN_ITEMS];
    int sum = 0;
#pragma unroll
    for (int i = 0; i < SCAN_ITEMS; i++) {
        int idx = base + i;
        int v = (idx < NTOT) ? g_cnt[idx] : 0;
        local[i] = sum;
        sum += v;
    }
    s[tid] = sum;
    __syncthreads();
    for (int o = 1; o < SCAN_BLK; o <<= 1) {
        int v = 0;
        if (tid >= o) v = s[tid - o];
        __syncthreads();
        s[tid] += v;
        __syncthreads();
    }
    int texcl = (tid == 0) ? 0 : s[tid - 1];
    int boff = boffs;
#pragma unroll
    for (int i = 0; i < SCAN_ITEMS; i++) {
        int idx = base + i;
        if (idx < NTOT) {
            int v = boff + texcl + local[i];
            g_rowstart[idx] = v;
            g_cursor[idx] = v;
        }
    }
}

__global__ void permute_kernel(const int* __restrict__ ei, int E)
{
    int t = blockIdx.y;
    int e = blockIdx.x * blockDim.x + threadIdx.x;
    if (e >= E) return;
    const int* src = ei + (size_t)(2 * t) * E;
    const int* dst = src + E;
    int d = __ldg(dst + e);
    int pos = atomicAdd(&g_cursor[type_off(t) + d], 1);
    g_csr[pos] = __ldg(src + e);
}

// ---------------- fused CSR-gather (fp16, shfl-broadcast) mean + GEMM + bias + ReLU + projection ----------------
template <int NMEAN>
__global__ __launch_bounds__(256, 4)
void transform_fused(const __half2* __restrict__ xs0, const int* __restrict__ rs0, const int* __restrict__ cn0,
                     const __half2* __restrict__ xs1, const int* __restrict__ rs1, const int* __restrict__ cn1,
                     const float* __restrict__ x,
                     const float* __restrict__ W0, const float* __restrict__ W1,
                     const float* __restrict__ Wr,
                     const float* __restrict__ bias,
                     const float* __restrict__ uvec,
                     float2* __restrict__ outp, int n)
{
    __shared__ __align__(16) float Ws[64][68];
    __shared__ __align__(16) float As[64][68];
    __shared__ float us[128];
    int tid = threadIdx.x;
    int row0 = blockIdx.x * 64;
    int cg = tid & 15, rg = tid >> 4;
    int c0 = cg * 4, r0 = rg * 4;
    int lane = tid & 31, wrp = tid >> 5;

    if (tid < 128) us[tid] = uvec[tid];

    float acc[4][4];
#pragma unroll
    for (int ci = 0; ci < 4; ci++) {
        float b = bias[c0 + ci];
#pragma unroll
        for (int ri = 0; ri < 4; ri++) acc[ri][ci] = b;
    }

    for (int p = 0; p <= NMEAN; ++p) {
        const float* W = (p == 0 && NMEAN >= 1) ? W0
                       : (p == 1 && NMEAN == 2) ? W1 : Wr;
#pragma unroll
        for (int i = 0; i < 16; i++) {
            int idx = tid + i * 256;
            Ws[idx >> 6][idx & 63] = W[idx];
        }

        if (p < NMEAN) {
            // CSR-gather mean: warp per row; one coalesced index load per 32 neighbors,
            // indices broadcast via shfl; unroll-8 feature loads for MLP.
            const __half2* xs = (p == 0) ? xs0 : xs1;
            const int* rs = (p == 0) ? rs0 : rs1;
            const int* cn = (p == 0) ? cn0 : cn1;
#pragma unroll 1
            for (int rr = 0; rr < 8; rr++) {
                int r = wrp * 8 + rr;
                int row = row0 + r;
                float ax = 0.f, ay = 0.f;
                float inv = 1.f;
                if (row < n) {
                    int start = __ldg(rs + row);
                    int c = __ldg(cn + row);
                    inv = 1.0f / fmaxf((float)c, 1.0f);
#pragma unroll 1
                    for (int jb = 0; jb < c; jb += 32) {
                        int li = jb + lane;
                        int myidx = (li < c) ? __ldg(&g_csr[start + li]) : 0;
                        int m = c - jb; if (m > 32) m = 32;
#pragma unroll 8
                        for (int q = 0; q < m; q++) {
                            int sidx = __shfl_sync(0xffffffffu, myidx, q);
                            float2 f = __half22float2(__ldg(xs + (size_t)sidx * 32 + lane));
                            ax += f.x; ay += f.y;
                        }
                    }
                }
                *(float2*)&As[r][lane * 2] = make_float2(ax * inv, ay * inv);
            }
        } else {
            // root features: coalesced direct fill (fp32)
#pragma unroll
            for (int i = 0; i < 16; i++) {
                int idx = tid + i * 256;
                int r = idx >> 6, c = idx & 63;
                int row = row0 + r;
                As[r][c] = (row < n) ? x[(size_t)row * 64 + c] : 0.f;
            }
        }
        __syncthreads();

#pragma unroll
        for (int k4 = 0; k4 < 16; k4++) {
            float4 a0 = *(const float4*)&As[r0 + 0][k4 * 4];
            float4 a1 = *(const float4*)&As[r0 + 1][k4 * 4];
            float4 a2 = *(const float4*)&As[r0 + 2][k4 * 4];
            float4 a3 = *(const float4*)&As[r0 + 3][k4 * 4];
#pragma unroll
            for (int kk = 0; kk < 4; kk++) {
                float4 wv = *(const float4*)&Ws[k4 * 4 + kk][c0];
                float f0 = (&a0.x)[kk];
                float f1 = (&a1.x)[kk];
                float f2 = (&a2.x)[kk];
                float f3 = (&a3.x)[kk];
                acc[0][0] += f0 * wv.x; acc[0][1] += f0 * wv.y; acc[0][2] += f0 * wv.z; acc[0][3] += f0 * wv.w;
                acc[1][0] += f1 * wv.x; acc[1][1] += f1 * wv.y; acc[1][2] += f1 * wv.z; acc[1][3] += f1 * wv.w;
                acc[2][0] += f2 * wv.x; acc[2][1] += f2 * wv.y; acc[2][2] += f2 * wv.z; acc[2][3] += f2 * wv.w;
                acc[3][0] += f3 * wv.x; acc[3][1] += f3 * wv.y; acc[3][2] += f3 * wv.z; acc[3][3] += f3 * wv.w;
            }
        }
        __syncthreads();
    }

    // relu(h1) -> As, then project to 2 dims with uvec
#pragma unroll
    for (int ri = 0; ri < 4; ri++)
#pragma unroll
        for (int ci = 0; ci < 4; ci++)
            As[r0 + ri][c0 + ci] = fmaxf(acc[ri][ci], 0.f);
    __syncthreads();

    if (tid < 64) {
        int row = row0 + tid;
        if (row < n) {
            float s0 = 0.f, s1 = 0.f;
#pragma unroll
            for (int k = 0; k < 64; k++) {
                float v = As[tid][k];
                s0 += v * us[2 * k + 0];
                s1 += v * us[2 * k + 1];
            }
            outp[row] = make_float2(s0, s1);
        }
    }
}

// ---------------- layer-2 scatter of 2-dim projections (1 thread/edge) ----------------
struct SPArgs {
    const float2* src[2];
    float2*       agg[2];
    const int*    es[2];
    const int*    ed[2];
};

__global__ void scatter_proj(SPArgs a, int E)
{
    int ty = blockIdx.y;
    int e = blockIdx.x * blockDim.x + threadIdx.x;
    if (e >= E) return;
    int s = __ldg(a.es[ty] + e);
    int d = __ldg(a.ed[ty] + e);
    float2 v = __ldg(a.src[ty] + s);
    float2* p = a.agg[ty] + d;
    asm volatile("red.global.add.v2.f32 [%0], {%1,%2};"
                 :: "l"(p), "f"(v.x), "f"(v.y) : "memory");
}

// ---------------- final: combine 2-dim pieces on gathered claims ----------------
__global__ void final_kernel(const float2* __restrict__ aggP0, const int* __restrict__ cn0,
                             const float2* __restrict__ aggP1, const int* __restrict__ cn1,
                             const float2* __restrict__ pc,
                             const int* __restrict__ bidx,
                             float2* __restrict__ out, int B)
{
    int b = blockIdx.x * blockDim.x + threadIdx.x;
    if (b >= B) return;
    int i = __ldg(bidx + b);
    float inv0 = 1.0f / fmaxf((float)__ldg(cn0 + i), 1.0f);
    float inv1 = 1.0f / fmaxf((float)__ldg(cn1 + i), 1.0f);
    float2 a0 = __ldg(aggP0 + i);
    float2 a1 = __ldg(aggP1 + i);
    float2 c  = __ldg(pc + i);
    float2 o;
    o.x = g_b2[0] + a0.x * inv0 + a1.x * inv1 + c.x;
    o.y = g_b2[1] + a0.y * inv0 + a1.y * inv1 + c.y;
    out[b] = o;
}

// ---------------- launch ----------------
extern "C" void kernel_launch(void* const* d_in, const int* in_sizes, int n_in,
                              void* d_out, int out_size)
{
    const float* x_claim  = (const float*)d_in[0];
    const float* x_entity = (const float*)d_in[1];
    const float* x_evid   = (const float*)d_in[2];
    const int*   ei       = (const int*)d_in[3];     // [4, 2, E]
    const int*   bidx     = (const int*)d_in[4];     // [B]
    const float* Wl1      = (const float*)d_in[5];   // [4,64,64]
    const float* bl1      = (const float*)d_in[6];   // [4,64]
    const float* Wr1      = (const float*)d_in[7];   // [4,64,64]
    const float* Wl2      = (const float*)d_in[8];
    const float* bl2      = (const float*)d_in[9];
    const float* Wr2      = (const float*)d_in[10];
    const float* Wc       = (const float*)d_in[11];  // [64,2]
    const float* bc       = (const float*)d_in[12];  // [2]
    float2* out = (float2*)d_out;

    const int E  = in_sizes[3] / 8;
    const int B  = in_sizes[4];
    const int nc = in_sizes[0] / 64;
    const int ne = in_sizes[1] / 64;
    const int nv = in_sizes[2] / 64;

    int *cnt, *rowstart;
    float *aggP, *pc, *pe, *pv, *Wr1c, *b1c, *u0, *u1, *ur;
    __half* xh;
    cudaGetSymbolAddress((void**)&cnt, g_cnt);
    cudaGetSymbolAddress((void**)&rowstart, g_rowstart);
    cudaGetSymbolAddress((void**)&aggP, g_aggP);
    cudaGetSymbolAddress((void**)&xh, g_xh);
    cudaGetSymbolAddress((void**)&pc, g_pc);
    cudaGetSymbolAddress((void**)&pe, g_pe);
    cudaGetSymbolAddress((void**)&pv, g_pv);
    cudaGetSymbolAddress((void**)&Wr1c, g_Wr1c);
    cudaGetSymbolAddress((void**)&b1c, g_b1c);
    cudaGetSymbolAddress((void**)&u0, g_u0);
    cudaGetSymbolAddress((void**)&u1, g_u1);
    cudaGetSymbolAddress((void**)&ur, g_ur);

    __half* xh_claim  = xh;
    __half* xh_entity = xh + (size_t)NC * 64;
    __half* xh_evid   = xh + (size_t)(NC + NE) * 64;

    prep_kernel<<<1, 256>>>(Wr1, bl1, Wl2, bl2, Wr2, Wc, bc);
    cudaMemsetAsync(cnt, 0, (size_t)NTOT * sizeof(int));
    cudaMemsetAsync(aggP, 0, (size_t)NC * 4 * sizeof(float));

    // fp16 feature conversion (single launch)
    THArgs th;
    th.src[0] = (const float4*)x_claim;  th.dst[0] = (__half2*)xh_claim;  th.n4[0] = nc * 16;
    th.src[1] = (const float4*)x_entity; th.dst[1] = (__half2*)xh_entity; th.n4[1] = ne * 16;
    th.src[2] = (const float4*)x_evid;   th.dst[2] = (__half2*)xh_evid;   th.n4[2] = nv * 16;
    int maxn4 = ne * 16;
    if (nc * 16 > maxn4) maxn4 = nc * 16;
    if (nv * 16 > maxn4) maxn4 = nv * 16;
    tohalf_kernel<<<dim3((maxn4 + 255) / 256, 3), 256>>>(th);

    const int eblk = (E + 255) / 256;

    // ---- CSR build ----
    hist_kernel<<<dim3(eblk, 4), 256>>>(ei, E);
    scan1_kernel<<<NSCAN, SCAN_BLK>>>();
    scan3_kernel<<<NSCAN, SCAN_BLK>>>();
    permute_kernel<<<dim3(eblk, 4), 256>>>(ei, E);

    // ---- fused gather-mean + transform -> 2-dim projections ----
    const int* cn0 = cnt;                 const int* rs0 = rowstart;               // entity->claim
    const int* cn1 = cnt + NC;            const int* rs1 = rowstart + NC;          // evidence->claim
    const int* cnE = cnt + 2 * NC;        const int* rsE = rowstart + 2 * NC;      // claim->entity
    const int* cnV = cnt + 2 * NC + NE;   const int* rsV = rowstart + 2 * NC + NE; // claim->evidence

    transform_fused<2><<<(nc + 63) / 64, 256>>>((const __half2*)xh_entity, rs0, cn0,
                                                (const __half2*)xh_evid,   rs1, cn1,
                                                x_claim,
                                                Wl1 + 0 * 4096, Wl1 + 1 * 4096, Wr1c, b1c,
                                                ur, (float2*)pc, nc);
    transform_fused<1><<<(ne + 63) / 64, 256>>>((const __half2*)xh_claim, rsE, cnE,
                                                nullptr, nullptr, nullptr,
                                                x_entity,
                                                Wl1 + 2 * 4096, nullptr, Wr1 + 2 * 4096, bl1 + 128,
                                                u0, (float2*)pe, ne);
    transform_fused<1><<<(nv + 63) / 64, 256>>>((const __half2*)xh_claim, rsV, cnV,
                                                nullptr, nullptr, nullptr,
                                                x_evid,
                                                Wl1 + 3 * 4096, nullptr, Wr1 + 3 * 4096, bl1 + 192,
                                                u1, (float2*)pv, nv);

    // ---- layer-2 scatter on 2-dim projections ----
    const size_t e2 = (size_t)2 * E;
    SPArgs a2;
    a2.src[0] = (const float2*)pe; a2.agg[0] = (float2*)aggP;
    a2.es[0] = ei + 0 * e2; a2.ed[0] = ei + 0 * e2 + E;
    a2.src[1] = (const float2*)pv; a2.agg[1] = (float2*)(aggP + 2 * NC);
    a2.es[1] = ei + 1 * e2; a2.ed[1] = ei + 1 * e2 + E;
    scatter_proj<<<dim3(eblk, 2), 256>>>(a2, E);

    // ---- final combine ----
    final_kernel<<<(B + 255) / 256, 256>>>((const float2*)aggP, cn0,
                                           (const float2*)(aggP + 2 * NC), cn1,
                                           (const float2*)pc, bidx, out, B);
}

// round 16
// speedup vs baseline: 1.1513x; 1.1513x over previous
#include <cuda_runtime.h>
#include <cuda_fp16.h>
#include <cstddef>

#define NC 100000
#define NE 200000
#define NV 150000
#define NTOT (2*NC + NE + NV)            // 550000 counters (type-concatenated)
#define SCAN_BLK 256
#define SCAN_ITEMS 16
#define SCAN_TILE (SCAN_BLK*SCAN_ITEMS)  // 4096
#define NSCAN ((NTOT + SCAN_TILE - 1)/SCAN_TILE)

// ---------------- scratch (static device globals) ----------------
__device__ int    g_cnt[NTOT];      // zeroed per run
__device__ float  g_aggP[NC * 4];   // zeroed per run: aggP0 | aggP1 (2 floats each)
__device__ int    g_rowstart[NTOT];
__device__ int    g_cursor[NTOT];
__device__ int    g_bsum[NSCAN];
__device__ int    g_csr[4 * 2000000];
__device__ __half g_xh[(NC + NE + NV) * 64];   // fp16 copies: claim | entity | evid
__device__ float  g_pc[NC * 2];     // relu(h1_claim) @ ur
__device__ float  g_pe[NE * 2];     // relu(h1_entity) @ u0
__device__ float  g_pv[NV * 2];     // relu(h1_evid) @ u1
__device__ float  g_Wr1c[64 * 64];  // Wr1[0] + Wr1[1]
__device__ float  g_b1c[64];        // bl1[0] + bl1[1]
__device__ float  g_u0[128];        // Wl2[0] @ Wc
__device__ float  g_u1[128];        // Wl2[1] @ Wc
__device__ float  g_ur[128];        // (Wr2[0]+Wr2[1]) @ Wc
__device__ float  g_b2[2];          // (bl2[0]+bl2[1]) @ Wc + bc

__device__ __forceinline__ int type_off(int t) {
    return (t == 0) ? 0 : (t == 1) ? NC : (t == 2) ? 2 * NC : 2 * NC + NE;
}

// ---------------- tiny weight prep ----------------
__global__ void prep_kernel(const float* __restrict__ Wr1, const float* __restrict__ bl1,
                            const float* __restrict__ Wl2, const float* __restrict__ bl2,
                            const float* __restrict__ Wr2, const float* __restrict__ Wc,
                            const float* __restrict__ bc)
{
    int tid = threadIdx.x;
    for (int idx = tid; idx < 4096; idx += 256)
        g_Wr1c[idx] = Wr1[idx] + Wr1[4096 + idx];
    if (tid < 64) g_b1c[tid] = bl1[tid] + bl1[64 + tid];
    if (tid < 128) {
        int i = tid >> 1, c = tid & 1;
        float s0 = 0.f, s1 = 0.f, sr = 0.f;
        for (int j = 0; j < 64; j++) {
            float wc = Wc[j * 2 + c];
            s0 += Wl2[i * 64 + j] * wc;
            s1 += Wl2[4096 + i * 64 + j] * wc;
            sr += (Wr2[i * 64 + j] + Wr2[4096 + i * 64 + j]) * wc;
        }
        g_u0[tid] = s0; g_u1[tid] = s1; g_ur[tid] = sr;
    }
    if (tid < 2) {
        float s = bc[tid];
        for (int j = 0; j < 64; j++) s += (bl2[j] + bl2[64 + j]) * Wc[j * 2 + tid];
        g_b2[tid] = s;
    }
}

// ---------------- fp32 -> fp16 feature conversion (all three tensors, one launch) ----------------
struct THArgs { const float4* src[3]; __half2* dst[3]; int n4[3]; };

__global__ void tohalf_kernel(THArgs a)
{
    int t = blockIdx.y;
    int i = blockIdx.x * blockDim.x + threadIdx.x;
    if (i >= a.n4[t]) return;
    float4 v = __ldg(a.src[t] + i);
    a.dst[t][2 * i]     = __floats2half2_rn(v.x, v.y);
    a.dst[t][2 * i + 1] = __floats2half2_rn(v.z, v.w);
}

// ---------------- CSR build: histogram / scan / permute ----------------
__global__ void hist_kernel(const int* __restrict__ ei, int E)
{
    int t = blockIdx.y;
    int e = blockIdx.x * blockDim.x + threadIdx.x;
    if (e >= E) return;
    const int* dst = ei + (size_t)(2 * t + 1) * E;
    atomicAdd(&g_cnt[type_off(t) + __ldg(dst + e)], 1);
}

__global__ void scan1_kernel()
{
    __shared__ int s[SCAN_BLK];
    int base = blockIdx.x * SCAN_TILE + threadIdx.x * SCAN_ITEMS;
    int sum = 0;
#pragma unroll
    for (int i = 0; i < SCAN_ITEMS; i++) {
        int idx = base + i;
        if (idx < NTOT) sum += g_cnt[idx];
    }
    s[threadIdx.x] = sum;
    __syncthreads();
    for (int o = SCAN_BLK / 2; o > 0; o >>= 1) {
        if (threadIdx.x < o) s[threadIdx.x] += s[threadIdx.x + o];
        __syncthreads();
    }
    if (threadIdx.x == 0) g_bsum[blockIdx.x] = s[0];
}

__global__ void scan3_kernel()
{
    __shared__ int s[SCAN_BLK];
    __shared__ int boffs;
    int tid = threadIdx.x;

    if (tid < 32) {
        int sum = 0;
        for (int i = tid; i < blockIdx.x; i += 32) sum += g_bsum[i];
#pragma unroll
        for (int o = 16; o > 0; o >>= 1)
            sum += __shfl_down_sync(0xffffffffu, sum, o);
        if (tid == 0) boffs = sum;
    }

    int base = blockIdx.x * SCAN_TILE + tid * SCAN_ITEMS;
    int local[SCAN_ITEMS];
    int sum = 0;
#pragma unroll
    for (int i = 0; i < SCAN_ITEMS; i++) {
        int idx = base + i;
        int v = (idx < NTOT) ? g_cnt[idx] : 0;
        local[i] = sum;
        sum += v;
    }
    s[tid] = sum;
    __syncthreads();
    for (int o = 1; o < SCAN_BLK; o <<= 1) {
        int v = 0;
        if (tid >= o) v = s[tid - o];
        __syncthreads();
        s[tid] += v;
        __syncthreads();
    }
    int texcl = (tid == 0) ? 0 : s[tid - 1];
    int boff = boffs;
#pragma unroll
    for (int i = 0; i < SCAN_ITEMS; i++) {
        int idx = base + i;
        if (idx < NTOT) {
            int v = boff + texcl + local[i];
            g_rowstart[idx] = v;
            g_cursor[idx] = v;
        }
    }
}

__global__ void permute_kernel(const int* __restrict__ ei, int E)
{
    int t = blockIdx.y;
    int e = blockIdx.x * blockDim.x + threadIdx.x;
    if (e >= E) return;
    const int* src = ei + (size_t)(2 * t) * E;
    const int* dst = src + E;
    int d = __ldg(dst + e);
    int pos = atomicAdd(&g_cursor[type_off(t) + d], 1);
    g_csr[pos] = __ldg(src + e);
}

// ---------------- fused CSR-gather (fp16, half-warp per row) + GEMM + ReLU + projection ----------------
template <int NMEAN>
__global__ __launch_bounds__(256, 4)
void transform_fused(const __half2* __restrict__ xs0, const int* __restrict__ rs0, const int* __restrict__ cn0,
                     const __half2* __restrict__ xs1, const int* __restrict__ rs1, const int* __restrict__ cn1,
                     const float* __restrict__ x,
                     const float* __restrict__ W0, const float* __restrict__ W1,
                     const float* __restrict__ Wr,
                     const float* __restrict__ bias,
                     const float* __restrict__ uvec,
                     float2* __restrict__ outp, int n)
{
    __shared__ __align__(16) float Ws[64][68];
    __shared__ __align__(16) float As[64][68];
    __shared__ float us[128];
    int tid = threadIdx.x;
    int row0 = blockIdx.x * 64;
    int cg = tid & 15, rg = tid >> 4;
    int c0 = cg * 4, r0 = rg * 4;
    int lane = tid & 31, wrp = tid >> 5;

    if (tid < 128) us[tid] = uvec[tid];

    float acc[4][4];
#pragma unroll
    for (int ci = 0; ci < 4; ci++) {
        float b = bias[c0 + ci];
#pragma unroll
        for (int ri = 0; ri < 4; ri++) acc[ri][ci] = b;
    }

    for (int p = 0; p <= NMEAN; ++p) {
        const float* W = (p == 0 && NMEAN >= 1) ? W0
                       : (p == 1 && NMEAN == 2) ? W1 : Wr;
#pragma unroll
        for (int i = 0; i < 16; i++) {
            int idx = tid + i * 256;
            Ws[idx >> 6][idx & 63] = W[idx];
        }

        if (p < NMEAN) {
            // CSR-gather mean: HALF-warp per row; lane&15 covers 4 halves via uint2,
            // lane>>4 picks one of two concurrent rows. Two load chains per warp.
            const __half2* xs = (p == 0) ? xs0 : xs1;
            const int* rs = (p == 0) ? rs0 : rs1;
            const int* cn = (p == 0) ? cn0 : cn1;
            int cl = lane & 15;
            int hw = lane >> 4;
#pragma unroll 1
            for (int rr = 0; rr < 4; rr++) {
                int r = wrp * 8 + rr * 2 + hw;
                int row = row0 + r;
                float a0 = 0.f, a1 = 0.f, a2 = 0.f, a3 = 0.f;
                float inv = 1.f;
                if (row < n) {
                    int start = __ldg(rs + row);
                    int c = __ldg(cn + row);
                    inv = 1.0f / fmaxf((float)c, 1.0f);
#pragma unroll 4
                    for (int j = 0; j < c; j++) {
                        int sidx = __ldg(&g_csr[start + j]);
                        uint2 v = __ldg((const uint2*)(xs + (size_t)sidx * 32) + cl);
                        float2 f0 = __half22float2(*(__half2*)&v.x);
                        float2 f1 = __half22float2(*(__half2*)&v.y);
                        a0 += f0.x; a1 += f0.y; a2 += f1.x; a3 += f1.y;
                    }
                }
                *(float4*)&As[r][cl * 4] = make_float4(a0 * inv, a1 * inv, a2 * inv, a3 * inv);
            }
        } else {
            // root features: coalesced direct fill (fp32)
#pragma unroll
            for (int i = 0; i < 16; i++) {
                int idx = tid + i * 256;
                int r = idx >> 6, c = idx & 63;
                int row = row0 + r;
                As[r][c] = (row < n) ? x[(size_t)row * 64 + c] : 0.f;
            }
        }
        __syncthreads();

#pragma unroll
        for (int k4 = 0; k4 < 16; k4++) {
            float4 a0 = *(const float4*)&As[r0 + 0][k4 * 4];
            float4 a1 = *(const float4*)&As[r0 + 1][k4 * 4];
            float4 a2 = *(const float4*)&As[r0 + 2][k4 * 4];
            float4 a3 = *(const float4*)&As[r0 + 3][k4 * 4];
#pragma unroll
            for (int kk = 0; kk < 4; kk++) {
                float4 wv = *(const float4*)&Ws[k4 * 4 + kk][c0];
                float f0 = (&a0.x)[kk];
                float f1 = (&a1.x)[kk];
                float f2 = (&a2.x)[kk];
                float f3 = (&a3.x)[kk];
                acc[0][0] += f0 * wv.x; acc[0][1] += f0 * wv.y; acc[0][2] += f0 * wv.z; acc[0][3] += f0 * wv.w;
                acc[1][0] += f1 * wv.x; acc[1][1] += f1 * wv.y; acc[1][2] += f1 * wv.z; acc[1][3] += f1 * wv.w;
                acc[2][0] += f2 * wv.x; acc[2][1] += f2 * wv.y; acc[2][2] += f2 * wv.z; acc[2][3] += f2 * wv.w;
                acc[3][0] += f3 * wv.x; acc[3][1] += f3 * wv.y; acc[3][2] += f3 * wv.z; acc[3][3] += f3 * wv.w;
            }
        }
        __syncthreads();
    }

    // relu(h1) -> As, then project to 2 dims with uvec
#pragma unroll
    for (int ri = 0; ri < 4; ri++)
#pragma unroll
        for (int ci = 0; ci < 4; ci++)
            As[r0 + ri][c0 + ci] = fmaxf(acc[ri][ci], 0.f);
    __syncthreads();

    if (tid < 64) {
        int row = row0 + tid;
        if (row < n) {
            float s0 = 0.f, s1 = 0.f;
#pragma unroll
            for (int k = 0; k < 64; k++) {
                float v = As[tid][k];
                s0 += v * us[2 * k + 0];
                s1 += v * us[2 * k + 1];
            }
            outp[row] = make_float2(s0, s1);
        }
    }
}

// ---------------- layer-2 scatter of 2-dim projections (1 thread/edge) ----------------
struct SPArgs {
    const float2* src[2];
    float2*       agg[2];
    const int*    es[2];
    const int*    ed[2];
};

__global__ void scatter_proj(SPArgs a, int E)
{
    int ty = blockIdx.y;
    int e = blockIdx.x * blockDim.x + threadIdx.x;
    if (e >= E) return;
    int s = __ldg(a.es[ty] + e);
    int d = __ldg(a.ed[ty] + e);
    float2 v = __ldg(a.src[ty] + s);
    float2* p = a.agg[ty] + d;
    asm volatile("red.global.add.v2.f32 [%0], {%1,%2};"
                 :: "l"(p), "f"(v.x), "f"(v.y) : "memory");
}

// ---------------- final: combine 2-dim pieces on gathered claims ----------------
__global__ void final_kernel(const float2* __restrict__ aggP0, const int* __restrict__ cn0,
                             const float2* __restrict__ aggP1, const int* __restrict__ cn1,
                             const float2* __restrict__ pc,
                             const int* __restrict__ bidx,
                             float2* __restrict__ out, int B)
{
    int b = blockIdx.x * blockDim.x + threadIdx.x;
    if (b >= B) return;
    int i = __ldg(bidx + b);
    float inv0 = 1.0f / fmaxf((float)__ldg(cn0 + i), 1.0f);
    float inv1 = 1.0f / fmaxf((float)__ldg(cn1 + i), 1.0f);
    float2 a0 = __ldg(aggP0 + i);
    float2 a1 = __ldg(aggP1 + i);
    float2 c  = __ldg(pc + i);
    float2 o;
    o.x = g_b2[0] + a0.x * inv0 + a1.x * inv1 + c.x;
    o.y = g_b2[1] + a0.y * inv0 + a1.y * inv1 + c.y;
    out[b] = o;
}

// ---------------- launch ----------------
extern "C" void kernel_launch(void* const* d_in, const int* in_sizes, int n_in,
                              void* d_out, int out_size)
{
    const float* x_claim  = (const float*)d_in[0];
    const float* x_entity = (const float*)d_in[1];
    const float* x_evid   = (const float*)d_in[2];
    const int*   ei       = (const int*)d_in[3];     // [4, 2, E]
    const int*   bidx     = (const int*)d_in[4];     // [B]
    const float* Wl1      = (const float*)d_in[5];   // [4,64,64]
    const float* bl1      = (const float*)d_in[6];   // [4,64]
    const float* Wr1      = (const float*)d_in[7];   // [4,64,64]
    const float* Wl2      = (const float*)d_in[8];
    const float* bl2      = (const float*)d_in[9];
    const float* Wr2      = (const float*)d_in[10];
    const float* Wc       = (const float*)d_in[11];  // [64,2]
    const float* bc       = (const float*)d_in[12];  // [2]
    float2* out = (float2*)d_out;

    const int E  = in_sizes[3] / 8;
    const int B  = in_sizes[4];
    const int nc = in_sizes[0] / 64;
    const int ne = in_sizes[1] / 64;
    const int nv = in_sizes[2] / 64;

    int *cnt, *rowstart;
    float *aggP, *pc, *pe, *pv, *Wr1c, *b1c, *u0, *u1, *ur;
    __half* xh;
    cudaGetSymbolAddress((void**)&cnt, g_cnt);
    cudaGetSymbolAddress((void**)&rowstart, g_rowstart);
    cudaGetSymbolAddress((void**)&aggP, g_aggP);
    cudaGetSymbolAddress((void**)&xh, g_xh);
    cudaGetSymbolAddress((void**)&pc, g_pc);
    cudaGetSymbolAddress((void**)&pe, g_pe);
    cudaGetSymbolAddress((void**)&pv, g_pv);
    cudaGetSymbolAddress((void**)&Wr1c, g_Wr1c);
    cudaGetSymbolAddress((void**)&b1c, g_b1c);
    cudaGetSymbolAddress((void**)&u0, g_u0);
    cudaGetSymbolAddress((void**)&u1, g_u1);
    cudaGetSymbolAddress((void**)&ur, g_ur);

    __half* xh_claim  = xh;
    __half* xh_entity = xh + (size_t)NC * 64;
    __half* xh_evid   = xh + (size_t)(NC + NE) * 64;

    prep_kernel<<<1, 256>>>(Wr1, bl1, Wl2, bl2, Wr2, Wc, bc);
    cudaMemsetAsync(cnt, 0, (size_t)NTOT * sizeof(int));
    cudaMemsetAsync(aggP, 0, (size_t)NC * 4 * sizeof(float));

    // fp16 feature conversion (single launch)
    THArgs th;
    th.src[0] = (const float4*)x_claim;  th.dst[0] = (__half2*)xh_claim;  th.n4[0] = nc * 16;
    th.src[1] = (const float4*)x_entity; th.dst[1] = (__half2*)xh_entity; th.n4[1] = ne * 16;
    th.src[2] = (const float4*)x_evid;   th.dst[2] = (__half2*)xh_evid;   th.n4[2] = nv * 16;
    int maxn4 = ne * 16;
    if (nc * 16 > maxn4) maxn4 = nc * 16;
    if (nv * 16 > maxn4) maxn4 = nv * 16;
    tohalf_kernel<<<dim3((maxn4 + 255) / 256, 3), 256>>>(th);

    const int eblk = (E + 255) / 256;

    // ---- CSR build ----
    hist_kernel<<<dim3(eblk, 4), 256>>>(ei, E);
    scan1_kernel<<<NSCAN, SCAN_BLK>>>();
    scan3_kernel<<<NSCAN, SCAN_BLK>>>();
    permute_kernel<<<dim3(eblk, 4), 256>>>(ei, E);

    // ---- fused gather-mean + transform -> 2-dim projections ----
    const int* cn0 = cnt;                 const int* rs0 = rowstart;               // entity->claim
    const int* cn1 = cnt + NC;            const int* rs1 = rowstart + NC;          // evidence->claim
    const int* cnE = cnt + 2 * NC;        const int* rsE = rowstart + 2 * NC;      // claim->entity
    const int* cnV = cnt + 2 * NC + NE;   const int* rsV = rowstart + 2 * NC + NE; // claim->evidence

    transform_fused<2><<<(nc + 63) / 64, 256>>>((const __half2*)xh_entity, rs0, cn0,
                                                (const __half2*)xh_evid,   rs1, cn1,
                                                x_claim,
                                                Wl1 + 0 * 4096, Wl1 + 1 * 4096, Wr1c, b1c,
                                                ur, (float2*)pc, nc);
    transform_fused<1><<<(ne + 63) / 64, 256>>>((const __half2*)xh_claim, rsE, cnE,
                                                nullptr, nullptr, nullptr,
                                                x_entity,
                                                Wl1 + 2 * 4096, nullptr, Wr1 + 2 * 4096, bl1 + 128,
                                                u0, (float2*)pe, ne);
    transform_fused<1><<<(nv + 63) / 64, 256>>>((const __half2*)xh_claim, rsV, cnV,
                                                nullptr, nullptr, nullptr,
                                                x_evid,
                                                Wl1 + 3 * 4096, nullptr, Wr1 + 3 * 4096, bl1 + 192,
                                                u1, (float2*)pv, nv);

    // ---- layer-2 scatter on 2-dim projections ----
    const size_t e2 = (size_t)2 * E;
    SPArgs a2;
    a2.src[0] = (const float2*)pe; a2.agg[0] = (float2*)aggP;
    a2.es[0] = ei + 0 * e2; a2.ed[0] = ei + 0 * e2 + E;
    a2.src[1] = (const float2*)pv; a2.agg[1] = (float2*)(aggP + 2 * NC);
    a2.es[1] = ei + 1 * e2; a2.ed[1] = ei + 1 * e2 + E;
    scatter_proj<<<dim3(eblk, 2), 256>>>(a2, E);

    // ---- final combine ----
    final_kernel<<<(B + 255) / 256, 256>>>((const float2*)aggP, cn0,
                                           (const float2*)(aggP + 2 * NC), cn1,
                                           (const float2*)pc, bidx, out, B);
}

// round 17
// speedup vs baseline: 1.1903x; 1.0339x over previous
#include <cuda_runtime.h>
#include <cuda_fp16.h>
#include <cstddef>

#define NC 100000
#define NE 200000
#define NV 150000
#define NTOT (2*NC + NE + NV)            // 550000 counters (type-concatenated)
#define SCAN_BLK 256
#define SCAN_ITEMS 16
#define SCAN_TILE (SCAN_BLK*SCAN_ITEMS)  // 4096
#define NSCAN ((NTOT + SCAN_TILE - 1)/SCAN_TILE)

// ---------------- scratch (static device globals) ----------------
__device__ int    g_cnt[NTOT];      // zeroed per run
__device__ float  g_aggP[NC * 4];   // zeroed per run: aggP0 | aggP1 (2 floats each)
__device__ int    g_rowstart[NTOT];
__device__ int    g_cursor[NTOT];
__device__ int    g_bsum[NSCAN];
__device__ int    g_csr[4 * 2000000];
__device__ __half g_xh[(NC + NE + NV) * 64];   // fp16 copies: claim | entity | evid
__device__ float  g_pc[NC * 2];     // relu(h1_claim) @ ur
__device__ float  g_pe[NE * 2];     // relu(h1_entity) @ u0
__device__ float  g_pv[NV * 2];     // relu(h1_evid) @ u1
__device__ float  g_Wr1c[64 * 64];  // Wr1[0] + Wr1[1]
__device__ float  g_b1c[64];        // bl1[0] + bl1[1]
__device__ float  g_u0[128];        // Wl2[0] @ Wc
__device__ float  g_u1[128];        // Wl2[1] @ Wc
__device__ float  g_ur[128];        // (Wr2[0]+Wr2[1]) @ Wc
__device__ float  g_b2[2];          // (bl2[0]+bl2[1]) @ Wc + bc

__device__ __forceinline__ int type_off(int t) {
    return (t == 0) ? 0 : (t == 1) ? NC : (t == 2) ? 2 * NC : 2 * NC + NE;
}

// ---------------- tiny weight prep ----------------
__global__ void prep_kernel(const float* __restrict__ Wr1, const float* __restrict__ bl1,
                            const float* __restrict__ Wl2, const float* __restrict__ bl2,
                            const float* __restrict__ Wr2, const float* __restrict__ Wc,
                            const float* __restrict__ bc)
{
    int tid = threadIdx.x;
    for (int idx = tid; idx < 4096; idx += 256)
        g_Wr1c[idx] = Wr1[idx] + Wr1[4096 + idx];
    if (tid < 64) g_b1c[tid] = bl1[tid] + bl1[64 + tid];
    if (tid < 128) {
        int i = tid >> 1, c = tid & 1;
        float s0 = 0.f, s1 = 0.f, sr = 0.f;
        for (int j = 0; j < 64; j++) {
            float wc = Wc[j * 2 + c];
            s0 += Wl2[i * 64 + j] * wc;
            s1 += Wl2[4096 + i * 64 + j] * wc;
            sr += (Wr2[i * 64 + j] + Wr2[4096 + i * 64 + j]) * wc;
        }
        g_u0[tid] = s0; g_u1[tid] = s1; g_ur[tid] = sr;
    }
    if (tid < 2) {
        float s = bc[tid];
        for (int j = 0; j < 64; j++) s += (bl2[j] + bl2[64 + j]) * Wc[j * 2 + tid];
        g_b2[tid] = s;
    }
}

// ---------------- fp32 -> fp16 feature conversion (all three tensors, one launch) ----------------
struct THArgs { const float4* src[3]; __half2* dst[3]; int n4[3]; };

__global__ void tohalf_kernel(THArgs a)
{
    int t = blockIdx.y;
    int i = blockIdx.x * blockDim.x + threadIdx.x;
    if (i >= a.n4[t]) return;
    float4 v = __ldg(a.src[t] + i);
    a.dst[t][2 * i]     = __floats2half2_rn(v.x, v.y);
    a.dst[t][2 * i + 1] = __floats2half2_rn(v.z, v.w);
}

// ---------------- CSR build: histogram / scan / permute ----------------
__global__ void hist_kernel(const int* __restrict__ ei, int E)
{
    int t = blockIdx.y;
    int e = blockIdx.x * blockDim.x + threadIdx.x;
    if (e >= E) return;
    const int* dst = ei + (size_t)(2 * t + 1) * E;
    atomicAdd(&g_cnt[type_off(t) + __ldg(dst + e)], 1);
}

__global__ void scan1_kernel()
{
    __shared__ int s[SCAN_BLK];
    int base = blockIdx.x * SCAN_TILE + threadIdx.x * SCAN_ITEMS;
    int sum = 0;
#pragma unroll
    for (int i = 0; i < SCAN_ITEMS; i++) {
        int idx = base + i;
        if (idx < NTOT) sum += g_cnt[idx];
    }
    s[threadIdx.x] = sum;
    __syncthreads();
    for (int o = SCAN_BLK / 2; o > 0; o >>= 1) {
        if (threadIdx.x < o) s[threadIdx.x] += s[threadIdx.x + o];
        __syncthreads();
    }
    if (threadIdx.x == 0) g_bsum[blockIdx.x] = s[0];
}

__global__ void scan3_kernel()
{
    __shared__ int s[SCAN_BLK];
    __shared__ int boffs;
    int tid = threadIdx.x;

    if (tid < 32) {
        int sum = 0;
        for (int i = tid; i < blockIdx.x; i += 32) sum += g_bsum[i];
#pragma unroll
        for (int o = 16; o > 0; o >>= 1)
            sum += __shfl_down_sync(0xffffffffu, sum, o);
        if (tid == 0) boffs = sum;
    }

    int base = blockIdx.x * SCAN_TILE + tid * SCAN_ITEMS;
    int local[SCAN_ITEMS];
    int sum = 0;
#pragma unroll
    for (int i = 0; i < SCAN_ITEMS; i++) {
        int idx = base + i;
        int v = (idx < NTOT) ? g_cnt[idx] : 0;
        local[i] = sum;
        sum += v;
    }
    s[tid] = sum;
    __syncthreads();
    for (int o = 1; o < SCAN_BLK; o <<= 1) {
        int v = 0;
        if (tid >= o) v = s[tid - o];
        __syncthreads();
        s[tid] += v;
        __syncthreads();
    }
    int texcl = (tid == 0) ? 0 : s[tid - 1];
    int boff = boffs;
#pragma unroll
    for (int i = 0; i < SCAN_ITEMS; i++) {
        int idx = base + i;
        if (idx < NTOT) {
            int v = boff + texcl + local[i];
            g_rowstart[idx] = v;
            g_cursor[idx] = v;
        }
    }
}

__global__ void permute_kernel(const int* __restrict__ ei, int E)
{
    int t = blockIdx.y;
    int e = blockIdx.x * blockDim.x + threadIdx.x;
    if (e >= E) return;
    const int* src = ei + (size_t)(2 * t) * E;
    const int* dst = src + E;
    int d = __ldg(dst + e);
    int pos = atomicAdd(&g_cursor[type_off(t) + d], 1);
    g_csr[pos] = __ldg(src + e);
}

// ---------------- fused CSR-gather (fp16, quarter-warp per row) + GEMM + ReLU + projection ----------------
template <int NMEAN>
__global__ __launch_bounds__(256, 4)
void transform_fused(const __half2* __restrict__ xs0, const int* __restrict__ rs0, const int* __restrict__ cn0,
                     const __half2* __restrict__ xs1, const int* __restrict__ rs1, const int* __restrict__ cn1,
                     const float* __restrict__ x,
                     const float* __restrict__ W0, const float* __restrict__ W1,
                     const float* __restrict__ Wr,
                     const float* __restrict__ bias,
                     const float* __restrict__ uvec,
                     float2* __restrict__ outp, int n)
{
    __shared__ __align__(16) float Ws[64][68];
    __shared__ __align__(16) float As[64][68];
    __shared__ float us[128];
    int tid = threadIdx.x;
    int row0 = blockIdx.x * 64;
    int cg = tid & 15, rg = tid >> 4;
    int c0 = cg * 4, r0 = rg * 4;
    int lane = tid & 31, wrp = tid >> 5;

    if (tid < 128) us[tid] = uvec[tid];

    float acc[4][4];
#pragma unroll
    for (int ci = 0; ci < 4; ci++) {
        float b = bias[c0 + ci];
#pragma unroll
        for (int ri = 0; ri < 4; ri++) acc[ri][ci] = b;
    }

    for (int p = 0; p <= NMEAN; ++p) {
        const float* W = (p == 0 && NMEAN >= 1) ? W0
                       : (p == 1 && NMEAN == 2) ? W1 : Wr;
#pragma unroll
        for (int i = 0; i < 16; i++) {
            int idx = tid + i * 256;
            Ws[idx >> 6][idx & 63] = W[idx];
        }

        if (p < NMEAN) {
            // CSR-gather mean: QUARTER-warp per row; lane&7 covers 8 halves via uint4,
            // lane>>3 picks one of four concurrent rows. Four load chains per warp.
            const __half2* xs = (p == 0) ? xs0 : xs1;
            const int* rs = (p == 0) ? rs0 : rs1;
            const int* cn = (p == 0) ? cn0 : cn1;
            int ql = lane & 7;
            int qw = lane >> 3;
#pragma unroll 1
            for (int rr = 0; rr < 2; rr++) {
                int r = wrp * 8 + rr * 4 + qw;
                int row = row0 + r;
                float a0 = 0.f, a1 = 0.f, a2 = 0.f, a3 = 0.f;
                float a4 = 0.f, a5 = 0.f, a6 = 0.f, a7 = 0.f;
                float inv = 1.f;
                if (row < n) {
                    int start = __ldg(rs + row);
                    int c = __ldg(cn + row);
                    inv = 1.0f / fmaxf((float)c, 1.0f);
#pragma unroll 4
                    for (int j = 0; j < c; j++) {
                        int sidx = __ldg(&g_csr[start + j]);
                        uint4 v = __ldg((const uint4*)(xs + (size_t)sidx * 32) + ql);
                        float2 f0 = __half22float2(*(__half2*)&v.x);
                        float2 f1 = __half22float2(*(__half2*)&v.y);
                        float2 f2 = __half22float2(*(__half2*)&v.z);
                        float2 f3 = __half22float2(*(__half2*)&v.w);
                        a0 += f0.x; a1 += f0.y; a2 += f1.x; a3 += f1.y;
                        a4 += f2.x; a5 += f2.y; a6 += f3.x; a7 += f3.y;
                    }
                }
                *(float4*)&As[r][ql * 8 + 0] = make_float4(a0 * inv, a1 * inv, a2 * inv, a3 * inv);
                *(float4*)&As[r][ql * 8 + 4] = make_float4(a4 * inv, a5 * inv, a6 * inv, a7 * inv);
            }
        } else {
            // root features: coalesced direct fill (fp32)
#pragma unroll
            for (int i = 0; i < 16; i++) {
                int idx = tid + i * 256;
                int r = idx >> 6, c = idx & 63;
                int row = row0 + r;
                As[r][c] = (row < n) ? x[(size_t)row * 64 + c] : 0.f;
            }
        }
        __syncthreads();

#pragma unroll
        for (int k4 = 0; k4 < 16; k4++) {
            float4 a0 = *(const float4*)&As[r0 + 0][k4 * 4];
            float4 a1 = *(const float4*)&As[r0 + 1][k4 * 4];
            float4 a2 = *(const float4*)&As[r0 + 2][k4 * 4];
            float4 a3 = *(const float4*)&As[r0 + 3][k4 * 4];
#pragma unroll
            for (int kk = 0; kk < 4; kk++) {
                float4 wv = *(const float4*)&Ws[k4 * 4 + kk][c0];
                float f0 = (&a0.x)[kk];
                float f1 = (&a1.x)[kk];
                float f2 = (&a2.x)[kk];
                float f3 = (&a3.x)[kk];
                acc[0][0] += f0 * wv.x; acc[0][1] += f0 * wv.y; acc[0][2] += f0 * wv.z; acc[0][3] += f0 * wv.w;
                acc[1][0] += f1 * wv.x; acc[1][1] += f1 * wv.y; acc[1][2] += f1 * wv.z; acc[1][3] += f1 * wv.w;
                acc[2][0] += f2 * wv.x; acc[2][1] += f2 * wv.y; acc[2][2] += f2 * wv.z; acc[2][3] += f2 * wv.w;
                acc[3][0] += f3 * wv.x; acc[3][1] += f3 * wv.y; acc[3][2] += f3 * wv.z; acc[3][3] += f3 * wv.w;
            }
        }
        __syncthreads();
    }

    // relu(h1) -> As, then project to 2 dims with uvec
#pragma unroll
    for (int ri = 0; ri < 4; ri++)
#pragma unroll
        for (int ci = 0; ci < 4; ci++)
            As[r0 + ri][c0 + ci] = fmaxf(acc[ri][ci], 0.f);
    __syncthreads();

    if (tid < 64) {
        int row = row0 + tid;
        if (row < n) {
            float s0 = 0.f, s1 = 0.f;
#pragma unroll
            for (int k = 0; k < 64; k++) {
                float v = As[tid][k];
                s0 += v * us[2 * k + 0];
                s1 += v * us[2 * k + 1];
            }
            outp[row] = make_float2(s0, s1);
        }
    }
}

// ---------------- layer-2 scatter of 2-dim projections (1 thread/edge) ----------------
struct SPArgs {
    const float2* src[2];
    float2*       agg[2];
    const int*    es[2];
    const int*    ed[2];
};

__global__ void scatter_proj(SPArgs a, int E)
{
    int ty = blockIdx.y;
    int e = blockIdx.x * blockDim.x + threadIdx.x;
    if (e >= E) return;
    int s = __ldg(a.es[ty] + e);
    int d = __ldg(a.ed[ty] + e);
    float2 v = __ldg(a.src[ty] + s);
    float2* p = a.agg[ty] + d;
    asm volatile("red.global.add.v2.f32 [%0], {%1,%2};"
                 :: "l"(p), "f"(v.x), "f"(v.y) : "memory");
}

// ---------------- final: combine 2-dim pieces on gathered claims ----------------
__global__ void final_kernel(const float2* __restrict__ aggP0, const int* __restrict__ cn0,
                             const float2* __restrict__ aggP1, const int* __restrict__ cn1,
                             const float2* __restrict__ pc,
                             const int* __restrict__ bidx,
                             float2* __restrict__ out, int B)
{
    int b = blockIdx.x * blockDim.x + threadIdx.x;
    if (b >= B) return;
    int i = __ldg(bidx + b);
    float inv0 = 1.0f / fmaxf((float)__ldg(cn0 + i), 1.0f);
    float inv1 = 1.0f / fmaxf((float)__ldg(cn1 + i), 1.0f);
    float2 a0 = __ldg(aggP0 + i);
    float2 a1 = __ldg(aggP1 + i);
    float2 c  = __ldg(pc + i);
    float2 o;
    o.x = g_b2[0] + a0.x * inv0 + a1.x * inv1 + c.x;
    o.y = g_b2[1] + a0.y * inv0 + a1.y * inv1 + c.y;
    out[b] = o;
}

// ---------------- launch ----------------
extern "C" void kernel_launch(void* const* d_in, const int* in_sizes, int n_in,
                              void* d_out, int out_size)
{
    const float* x_claim  = (const float*)d_in[0];
    const float* x_entity = (const float*)d_in[1];
    const float* x_evid   = (const float*)d_in[2];
    const int*   ei       = (const int*)d_in[3];     // [4, 2, E]
    const int*   bidx     = (const int*)d_in[4];     // [B]
    const float* Wl1      = (const float*)d_in[5];   // [4,64,64]
    const float* bl1      = (const float*)d_in[6];   // [4,64]
    const float* Wr1      = (const float*)d_in[7];   // [4,64,64]
    const float* Wl2      = (const float*)d_in[8];
    const float* bl2      = (const float*)d_in[9];
    const float* Wr2      = (const float*)d_in[10];
    const float* Wc       = (const float*)d_in[11];  // [64,2]
    const float* bc       = (const float*)d_in[12];  // [2]
    float2* out = (float2*)d_out;

    const int E  = in_sizes[3] / 8;
    const int B  = in_sizes[4];
    const int nc = in_sizes[0] / 64;
    const int ne = in_sizes[1] / 64;
    const int nv = in_sizes[2] / 64;

    int *cnt, *rowstart;
    float *aggP, *pc, *pe, *pv, *Wr1c, *b1c, *u0, *u1, *ur;
    __half* xh;
    cudaGetSymbolAddress((void**)&cnt, g_cnt);
    cudaGetSymbolAddress((void**)&rowstart, g_rowstart);
    cudaGetSymbolAddress((void**)&aggP, g_aggP);
    cudaGetSymbolAddress((void**)&xh, g_xh);
    cudaGetSymbolAddress((void**)&pc, g_pc);
    cudaGetSymbolAddress((void**)&pe, g_pe);
    cudaGetSymbolAddress((void**)&pv, g_pv);
    cudaGetSymbolAddress((void**)&Wr1c, g_Wr1c);
    cudaGetSymbolAddress((void**)&b1c, g_b1c);
    cudaGetSymbolAddress((void**)&u0, g_u0);
    cudaGetSymbolAddress((void**)&u1, g_u1);
    cudaGetSymbolAddress((void**)&ur, g_ur);

    __half* xh_claim  = xh;
    __half* xh_entity = xh + (size_t)NC * 64;
    __half* xh_evid   = xh + (size_t)(NC + NE) * 64;

    prep_kernel<<<1, 256>>>(Wr1, bl1, Wl2, bl2, Wr2, Wc, bc);
    cudaMemsetAsync(cnt, 0, (size_t)NTOT * sizeof(int));
    cudaMemsetAsync(aggP, 0, (size_t)NC * 4 * sizeof(float));

    // fp16 feature conversion (single launch)
    THArgs th;
    th.src[0] = (const float4*)x_claim;  th.dst[0] = (__half2*)xh_claim;  th.n4[0] = nc * 16;
    th.src[1] = (const float4*)x_entity; th.dst[1] = (__half2*)xh_entity; th.n4[1] = ne * 16;
    th.src[2] = (const float4*)x_evid;   th.dst[2] = (__half2*)xh_evid;   th.n4[2] = nv * 16;
    int maxn4 = ne * 16;
    if (nc * 16 > maxn4) maxn4 = nc * 16;
    if (nv * 16 > maxn4) maxn4 = nv * 16;
    tohalf_kernel<<<dim3((maxn4 + 255) / 256, 3), 256>>>(th);

    const int eblk = (E + 255) / 256;

    // ---- CSR build ----
    hist_kernel<<<dim3(eblk, 4), 256>>>(ei, E);
    scan1_kernel<<<NSCAN, SCAN_BLK>>>();
    scan3_kernel<<<NSCAN, SCAN_BLK>>>();
    permute_kernel<<<dim3(eblk, 4), 256>>>(ei, E);

    // ---- fused gather-mean + transform -> 2-dim projections ----
    const int* cn0 = cnt;                 const int* rs0 = rowstart;               // entity->claim
    const int* cn1 = cnt + NC;            const int* rs1 = rowstart + NC;          // evidence->claim
    const int* cnE = cnt + 2 * NC;        const int* rsE = rowstart + 2 * NC;      // claim->entity
    const int* cnV = cnt + 2 * NC + NE;   const int* rsV = rowstart + 2 * NC + NE; // claim->evidence

    transform_fused<2><<<(nc + 63) / 64, 256>>>((const __half2*)xh_entity, rs0, cn0,
                                                (const __half2*)xh_evid,   rs1, cn1,
                                                x_claim,
                                                Wl1 + 0 * 4096, Wl1 + 1 * 4096, Wr1c, b1c,
                                                ur, (float2*)pc, nc);
    transform_fused<1><<<(ne + 63) / 64, 256>>>((const __half2*)xh_claim, rsE, cnE,
                                                nullptr, nullptr, nullptr,
                                                x_entity,
                                                Wl1 + 2 * 4096, nullptr, Wr1 + 2 * 4096, bl1 + 128,
                                                u0, (float2*)pe, ne);
    transform_fused<1><<<(nv + 63) / 64, 256>>>((const __half2*)xh_claim, rsV, cnV,
                                                nullptr, nullptr, nullptr,
                                                x_evid,
                                                Wl1 + 3 * 4096, nullptr, Wr1 + 3 * 4096, bl1 + 192,
                                                u1, (float2*)pv, nv);

    // ---- layer-2 scatter on 2-dim projections ----
    const size_t e2 = (size_t)2 * E;
    SPArgs a2;
    a2.src[0] = (const float2*)pe; a2.agg[0] = (float2*)aggP;
    a2.es[0] = ei + 0 * e2; a2.ed[0] = ei + 0 * e2 + E;
    a2.src[1] = (const float2*)pv; a2.agg[1] = (float2*)(aggP + 2 * NC);
    a2.es[1] = ei + 1 * e2; a2.ed[1] = ei + 1 * e2 + E;
    scatter_proj<<<dim3(eblk, 2), 256>>>(a2, E);

    // ---- final combine ----
    final_kernel<<<(B + 255) / 256, 256>>>((const float2*)aggP, cn0,
                                           (const float2*)(aggP + 2 * NC), cn1,
                                           (const float2*)pc, bidx, out, B);
}